// round 8
// baseline (speedup 1.0000x reference)
#include <cuda_runtime.h>
#include <cuda_bf16.h>

// FCOS loss: focal cls + centerness BCE + GIoU reg.
// Phase 1: flat linear stream over all cls logits (bulk focal sum).
// Phase 2: per-position losses + matched-channel focal fixup (gather).
// B=16, C=80, S=17064, levels hw = {12800,3200,800,208,56}.

#define BATCH 16
#define NCLS 80
#define STOT 17064
#define NCHUNK 36                 // 25+7+2+1+1 chunks of 512 positions
#define NBLK (BATCH * NCHUNK)     // 576 blocks
#define FLAT4 5460480             // total cls float4s (21,841,920 floats / 4)
#define PER_BLK 9480              // FLAT4 / NBLK (exact)
#define C_NM 0.5198603854199589f  // 0.75 * ln2
#define C_M  0.17328679513998632f // 0.25 * ln2
#define L2E  1.4426950408889634f
#define LN2  0.6931471805599453f

// level edges in float4 units within the virtual concat of cls arrays
#define E1 4096000   // end lvl0 (16*80*12800/4)
#define E2 5120000   // + 16*80*3200/4
#define E3 5376000   // + 16*80*800/4
#define E4 5442560   // + 16*80*208/4

struct Ptrs {
    const float* cls[5];
    const float* cnt[5];
    const float* reg[5];
};

__device__ float g_cls[NBLK];
__device__ float g_cnt[NBLK];
__device__ float g_reg[NBLK];
__device__ float g_pos[NBLK];
__device__ int   g_sem;           // zero-init; reset by last block each call

__device__ __forceinline__ float wsum(float v) {
    #pragma unroll
    for (int o = 16; o; o >>= 1) v += __shfl_down_sync(0xffffffffu, v, o);
    return v;
}

// log2(1+e^x) * sigmoid(x)^2 accumulated into acc (caller scales by a*ln2)
__device__ __forceinline__ void focal_acc(float x, float& acc) {
    float e  = exp2f(x * L2E);        // MUFU.EX2
    float u  = 1.f + e;
    float sp = __log2f(u);            // MUFU.LG2
    float sg = __fdividef(e, u);      // MUFU.RCP + FMUL
    acc = fmaf(sp, sg * sg, acc);
}

__device__ __forceinline__ float focal_one(float x) {
    float a = 0.f; focal_acc(x, a); return a;
}

// flat float4 index -> address within the proper cls level
__device__ __forceinline__ const float4* flat_addr(const Ptrs& P, int f) {
    int lvl = (f >= E1) + (f >= E2) + (f >= E3) + (f >= E4);
    int e   = (f >= E4) ? E4 : (f >= E3) ? E3 : (f >= E2) ? E2 : (f >= E1) ? E1 : 0;
    return reinterpret_cast<const float4*>(P.cls[lvl]) + (f - e);
}

__global__ __launch_bounds__(256) void k_main(
    Ptrs P,
    const float* __restrict__ cnt_t,
    const float* __restrict__ reg_t,
    const int* __restrict__ cls_t32,   // int32 view; may actually be int64 data
    float* __restrict__ out)
{
    int bid = blockIdx.x;
    int tid = threadIdx.x;
    int lane = tid & 31;

    // ================= Phase 1: flat focal stream =================
    // block range [lo, lo+PER_BLK); thread t handles lo+t, lo+t+256, ...
    int lo = bid * PER_BLK;
    int n  = (PER_BLK - tid + 255) >> 8;   // 38 for tid<8, else 37

    float ac0 = 0.f, ac1 = 0.f, ac2 = 0.f, ac3 = 0.f;
    float4 buf[4];
    #pragma unroll
    for (int k = 0; k < 4; k++)
        if (k < n) buf[k] = __ldg(flat_addr(P, lo + tid + (k << 8)));

    for (int i = 0; i < n; i++) {
        float4 x = buf[i & 3];
        if (i + 4 < n) buf[i & 3] = __ldg(flat_addr(P, lo + tid + ((i + 4) << 8)));
        focal_acc(x.x, ac0);
        focal_acc(x.y, ac1);
        focal_acc(x.z, ac2);
        focal_acc(x.w, ac3);
    }
    float a_cls = C_NM * ((ac0 + ac1) + (ac2 + ac3));

    // ================= Phase 2: per-position losses =================
    int b = bid / NCHUNK;
    int chunk = bid - b * NCHUNK;
    int hw, sb, base, lvl;
    if (chunk < 25)      { hw = 12800; sb = 0;     base = chunk << 9;        lvl = 0; }
    else if (chunk < 32) { hw = 3200;  sb = 12800; base = (chunk - 25) << 9; lvl = 1; }
    else if (chunk < 34) { hw = 800;   sb = 16000; base = (chunk - 32) << 9; lvl = 2; }
    else if (chunk < 35) { hw = 208;   sb = 16800; base = 0;                 lvl = 3; }
    else                 { hw = 56;    sb = 17008; base = 0;                 lvl = 4; }

    // dtype sniff: little-endian int64 -> odd int32 words (high words) are 0.
    int probe = cls_t32[2 * lane + 1];
    bool is64 = (__ballot_sync(0xffffffffu, probe != 0) == 0u);

    int p0 = base + 2 * tid;                 // adjacent pair (hw always even)
    bool v = p0 < hw;
    int p0c = v ? p0 : 0;
    size_t ti = (size_t)b * STOT + sb + p0c;
    int hw2 = hw >> 1;

    int tgt0, tgt1;
    if (is64) {
        int4 tw = __ldg(reinterpret_cast<const int4*>(cls_t32 + 2 * ti));
        tgt0 = tw.x; tgt1 = tw.z;
    } else {
        int2 tw = __ldg(reinterpret_cast<const int2*>(cls_t32 + ti));
        tgt0 = tw.x; tgt1 = tw.y;
    }
    float2 ct = __ldg(reinterpret_cast<const float2*>(cnt_t + ti));

    float a_cnt = 0.f, a_reg = 0.f, a_pos = 0.f;

    if (v) {
        bool m0 = ct.x > -1.0f;
        bool m1 = ct.y > -1.0f;
        a_pos = (m0 ? 1.f : 0.f) + (m1 ? 1.f : 0.f);

        float2 cv = __ldg(reinterpret_cast<const float2*>(
                          P.cnt[lvl] + (size_t)b * hw + p0c));
        const float2* rp2 = reinterpret_cast<const float2*>(
                            P.reg[lvl] + (size_t)b * 4 * hw + p0c);
        float2 L = __ldg(rp2);
        float2 T = __ldg(rp2 + hw2);
        float2 R = __ldg(rp2 + 2 * hw2);
        float2 Bo = __ldg(rp2 + 3 * hw2);
        float4 rt0 = __ldg(reinterpret_cast<const float4*>(reg_t + ti * 4));
        float4 rt1 = __ldg(reinterpret_cast<const float4*>(reg_t + ti * 4 + 4));

        if (m0) {
            float e = exp2f(-fabsf(cv.x) * L2E);
            a_cnt += fmaxf(cv.x, 0.f) - cv.x * ct.x + LN2 * __log2f(1.f + e);
            float wmin = fmaxf(fminf(R.x, rt0.z) + fminf(L.x, rt0.x), 0.f);
            float hmin = fmaxf(fminf(Bo.x, rt0.w) + fminf(T.x, rt0.y), 0.f);
            float ov   = wmin * hmin;
            float uni  = (R.x + L.x) * (Bo.x + T.x) + (rt0.z + rt0.x) * (rt0.w + rt0.y) - ov;
            float wmax = fmaxf(fmaxf(R.x, rt0.z) + fmaxf(L.x, rt0.x), 0.f);
            float hmax = fmaxf(fmaxf(Bo.x, rt0.w) + fmaxf(T.x, rt0.y), 0.f);
            float ga   = wmax * hmax;
            a_reg += 1.f - __fdividef(ov, uni) + __fdividef(ga - uni, fmaxf(ga, 1e-10f));
        }
        if (m1) {
            float e = exp2f(-fabsf(cv.y) * L2E);
            a_cnt += fmaxf(cv.y, 0.f) - cv.y * ct.y + LN2 * __log2f(1.f + e);
            float wmin = fmaxf(fminf(R.y, rt1.z) + fminf(L.y, rt1.x), 0.f);
            float hmin = fmaxf(fminf(Bo.y, rt1.w) + fminf(T.y, rt1.y), 0.f);
            float ov   = wmin * hmin;
            float uni  = (R.y + L.y) * (Bo.y + T.y) + (rt1.z + rt1.x) * (rt1.w + rt1.y) - ov;
            float wmax = fmaxf(fmaxf(R.y, rt1.z) + fmaxf(L.y, rt1.x), 0.f);
            float hmax = fmaxf(fmaxf(Bo.y, rt1.w) + fmaxf(T.y, rt1.y), 0.f);
            float ga   = wmax * hmax;
            a_reg += 1.f - __fdividef(ov, uni) + __fdividef(ga - uni, fmaxf(ga, 1e-10f));
        }

        // focal fixup gathers (matched channel per position, tgt in 1..80)
        const float* cb = P.cls[lvl] + (size_t)b * NCLS * hw;
        if ((unsigned)(tgt0 - 1) < NCLS) {
            float x = __ldg(cb + (size_t)(tgt0 - 1) * hw + p0c);
            a_cls += C_M * focal_one(-x) - C_NM * focal_one(x);
        }
        if ((unsigned)(tgt1 - 1) < NCLS) {
            float x = __ldg(cb + (size_t)(tgt1 - 1) * hw + p0c + 1);
            a_cls += C_M * focal_one(-x) - C_NM * focal_one(x);
        }
    }

    // ---- block reduction into per-block slots (deterministic) ----
    a_cls = wsum(a_cls); a_cnt = wsum(a_cnt); a_reg = wsum(a_reg); a_pos = wsum(a_pos);

    __shared__ float sm[8][4];
    int w = tid >> 5;
    if (lane == 0) { sm[w][0] = a_cls; sm[w][1] = a_cnt; sm[w][2] = a_reg; sm[w][3] = a_pos; }
    __syncthreads();
    if (w == 0 && lane < 8) {
        float x0 = sm[lane][0], x1 = sm[lane][1], x2 = sm[lane][2], x3 = sm[lane][3];
        #pragma unroll
        for (int o = 4; o; o >>= 1) {
            x0 += __shfl_down_sync(0xffu, x0, o);
            x1 += __shfl_down_sync(0xffu, x1, o);
            x2 += __shfl_down_sync(0xffu, x2, o);
            x3 += __shfl_down_sync(0xffu, x3, o);
        }
        if (lane == 0) {
            g_cls[bid] = x0; g_cnt[bid] = x1; g_reg[bid] = x2; g_pos[bid] = x3;
        }
    }

    // ---- last block finishes: parallel final combine ----
    __shared__ bool is_last;
    __threadfence();
    if (tid == 0) is_last = (atomicAdd(&g_sem, 1) == NBLK - 1);
    __syncthreads();
    if (!is_last) return;

    int bt = tid >> 4;       // batch 0..15
    int j  = tid & 15;
    float cls = 0.f, cnt = 0.f, reg = 0.f, pos = 0.f;
    for (int c = j; c < NCHUNK; c += 16) {
        int i = bt * NCHUNK + c;
        cls += g_cls[i]; cnt += g_cnt[i]; reg += g_reg[i]; pos += g_pos[i];
    }
    #pragma unroll
    for (int o = 8; o; o >>= 1) {
        cls += __shfl_down_sync(0xffffffffu, cls, o, 16);
        cnt += __shfl_down_sync(0xffffffffu, cnt, o, 16);
        reg += __shfl_down_sync(0xffffffffu, reg, o, 16);
        pos += __shfl_down_sync(0xffffffffu, pos, o, 16);
    }
    __shared__ float s3[16][3];
    if (j == 0) {
        float np = fmaxf(pos, 1.f);
        s3[bt][0] = cls / np; s3[bt][1] = cnt / np; s3[bt][2] = reg / np;
    }
    __syncthreads();
    if (tid < 16) {
        float c0 = s3[tid][0], c1 = s3[tid][1], c2 = s3[tid][2];
        #pragma unroll
        for (int o = 8; o; o >>= 1) {
            c0 += __shfl_down_sync(0xffffu, c0, o, 16);
            c1 += __shfl_down_sync(0xffffu, c1, o, 16);
            c2 += __shfl_down_sync(0xffffu, c2, o, 16);
        }
        if (tid == 0) {
            c0 *= (1.f / BATCH); c1 *= (1.f / BATCH); c2 *= (1.f / BATCH);
            out[0] = c0; out[1] = c1; out[2] = c2; out[3] = c0 + c1 + c2;
            g_sem = 0;   // reset for next graph replay
        }
    }
}

extern "C" void kernel_launch(void* const* d_in, const int* in_sizes, int n_in,
                              void* d_out, int out_size)
{
    // Three candidate input orderings, disambiguated by element counts:
    //  interleaved (dict):    in_sizes[1] = cnt_p0 = 204800
    //  alphabetical (names):  in_sizes[5] = cls_targets = 273024
    //  grouped (signature):   otherwise
    Ptrs P;
    const float* cnt_t;
    const float* reg_t;
    const int*   cls_t;

    if (in_sizes[1] == 204800) {                    // interleaved
        for (int i = 0; i < 5; i++) {
            P.cls[i] = (const float*)d_in[3 * i + 0];
            P.cnt[i] = (const float*)d_in[3 * i + 1];
            P.reg[i] = (const float*)d_in[3 * i + 2];
        }
        cnt_t = (const float*)d_in[15];
        reg_t = (const float*)d_in[16];
        cls_t = (const int*)d_in[17];
    } else if (in_sizes[5] == 273024) {             // alphabetical
        for (int i = 0; i < 5; i++) {
            P.cls[i] = (const float*)d_in[i];
            P.cnt[i] = (const float*)d_in[6 + i];
            P.reg[i] = (const float*)d_in[12 + i];
        }
        cls_t = (const int*)d_in[5];
        cnt_t = (const float*)d_in[11];
        reg_t = (const float*)d_in[17];
    } else {                                        // grouped (signature order)
        for (int i = 0; i < 5; i++) {
            P.cls[i] = (const float*)d_in[i];
            P.cnt[i] = (const float*)d_in[5 + i];
            P.reg[i] = (const float*)d_in[10 + i];
        }
        cnt_t = (const float*)d_in[15];
        reg_t = (const float*)d_in[16];
        cls_t = (const int*)d_in[17];
    }

    k_main<<<NBLK, 256>>>(P, cnt_t, reg_t, cls_t, (float*)d_out);
}

// round 9
// speedup vs baseline: 1.6675x; 1.6675x over previous
#include <cuda_runtime.h>
#include <cuda_bf16.h>

// FCOS loss: focal cls + centerness BCE + GIoU reg.
// Phase 1: flat linear stream over cls logits, segmented per level (<=2 segs/block),
//          statically batched 8x float4 loads (MLP 8), evict-first (.cs).
// Phase 2: per-position losses + matched-channel focal fixup (gather).
// B=16, C=80, S=17064, levels hw = {12800,3200,800,208,56}.

#define BATCH 16
#define NCLS 80
#define STOT 17064
#define NCHUNK 36                 // 25+7+2+1+1 chunks of 512 positions
#define NBLK (BATCH * NCHUNK)     // 576 blocks
#define FLAT4 5460480             // total cls float4s
#define PER_BLK 9480              // FLAT4 / NBLK (exact)
#define C_NM 0.5198603854199589f  // 0.75 * ln2
#define C_M  0.17328679513998632f // 0.25 * ln2
#define L2E  1.4426950408889634f
#define LN2  0.6931471805599453f

// level edges in float4 units within the virtual concat of cls arrays
#define E1 4096000
#define E2 5120000
#define E3 5376000
#define E4 5442560

struct Ptrs {
    const float* cls[5];
    const float* cnt[5];
    const float* reg[5];
};

__device__ float g_cls[NBLK];
__device__ float g_cnt[NBLK];
__device__ float g_reg[NBLK];
__device__ float g_pos[NBLK];
__device__ int   g_sem;           // zero-init; reset by last block each call

__device__ __forceinline__ float wsum(float v) {
    #pragma unroll
    for (int o = 16; o; o >>= 1) v += __shfl_down_sync(0xffffffffu, v, o);
    return v;
}

// log2(1+e^x) * sigmoid(x)^2 accumulated into acc (caller scales by a*ln2)
__device__ __forceinline__ void focal_acc(float x, float& acc) {
    float e  = exp2f(x * L2E);        // MUFU.EX2
    float u  = 1.f + e;
    float sp = __log2f(u);            // MUFU.LG2
    float sg = __fdividef(e, u);      // MUFU.RCP + FMUL
    acc = fmaf(sp, sg * sg, acc);
}

__device__ __forceinline__ float focal_one(float x) {
    float a = 0.f; focal_acc(x, a); return a;
}

__global__ __launch_bounds__(256) void k_main(
    Ptrs P,
    const float* __restrict__ cnt_t,
    const float* __restrict__ reg_t,
    const int* __restrict__ cls_t32,   // int32 view; may actually be int64 data
    float* __restrict__ out)
{
    int bid = blockIdx.x;
    int tid = threadIdx.x;
    int lane = tid & 31;

    // ================= Phase 1: segmented flat focal stream =================
    int lo = bid * PER_BLK;
    int hi = lo + PER_BLK;
    float ac0 = 0.f, ac1 = 0.f, ac2 = 0.f, ac3 = 0.f;

    #pragma unroll 1
    while (lo < hi) {
        int slvl, e0, e1;
        if (lo < E1)      { slvl = 0; e0 = 0;  e1 = E1; }
        else if (lo < E2) { slvl = 1; e0 = E1; e1 = E2; }
        else if (lo < E3) { slvl = 2; e0 = E2; e1 = E3; }
        else if (lo < E4) { slvl = 3; e0 = E3; e1 = E4; }
        else              { slvl = 4; e0 = E4; e1 = FLAT4; }
        int send = hi < e1 ? hi : e1;
        const float4* base = reinterpret_cast<const float4*>(P.cls[slvl]) + (lo - e0);
        int len = send - lo;

        int full = len >> 11;                  // tiles of 2048 float4
        for (int t = 0; t < full; t++) {
            const float4* p = base + (t << 11) + tid;
            float4 v[8];
            #pragma unroll
            for (int k = 0; k < 8; k++) v[k] = __ldcs(p + (k << 8));
            #pragma unroll
            for (int k = 0; k < 8; k++) {
                focal_acc(v[k].x, ac0);
                focal_acc(v[k].y, ac1);
                focal_acc(v[k].z, ac2);
                focal_acc(v[k].w, ac3);
            }
        }
        #pragma unroll 4
        for (int j = (full << 11) + tid; j < len; j += 256) {
            float4 v = __ldcs(base + j);
            focal_acc(v.x, ac0);
            focal_acc(v.y, ac1);
            focal_acc(v.z, ac2);
            focal_acc(v.w, ac3);
        }
        lo = send;
    }
    float a_cls = C_NM * ((ac0 + ac1) + (ac2 + ac3));

    // ================= Phase 2: per-position losses =================
    int b = bid / NCHUNK;
    int chunk = bid - b * NCHUNK;
    int hw, sb, base2, lvl;
    if (chunk < 25)      { hw = 12800; sb = 0;     base2 = chunk << 9;        lvl = 0; }
    else if (chunk < 32) { hw = 3200;  sb = 12800; base2 = (chunk - 25) << 9; lvl = 1; }
    else if (chunk < 34) { hw = 800;   sb = 16000; base2 = (chunk - 32) << 9; lvl = 2; }
    else if (chunk < 35) { hw = 208;   sb = 16800; base2 = 0;                 lvl = 3; }
    else                 { hw = 56;    sb = 17008; base2 = 0;                 lvl = 4; }

    // dtype sniff: little-endian int64 -> odd int32 words (high words) are 0.
    int probe = cls_t32[2 * lane + 1];
    bool is64 = (__ballot_sync(0xffffffffu, probe != 0) == 0u);

    int p0 = base2 + 2 * tid;                 // adjacent pair (hw always even)
    bool v = p0 < hw;
    int p0c = v ? p0 : 0;
    size_t ti = (size_t)b * STOT + sb + p0c;
    int hw2 = hw >> 1;

    int tgt0, tgt1;
    if (is64) {
        int4 tw = __ldg(reinterpret_cast<const int4*>(cls_t32 + 2 * ti));
        tgt0 = tw.x; tgt1 = tw.z;
    } else {
        int2 tw = __ldg(reinterpret_cast<const int2*>(cls_t32 + ti));
        tgt0 = tw.x; tgt1 = tw.y;
    }
    float2 ct = __ldg(reinterpret_cast<const float2*>(cnt_t + ti));

    float a_cnt = 0.f, a_reg = 0.f, a_pos = 0.f;

    if (v) {
        bool m0 = ct.x > -1.0f;
        bool m1 = ct.y > -1.0f;
        a_pos = (m0 ? 1.f : 0.f) + (m1 ? 1.f : 0.f);

        float2 cv = __ldg(reinterpret_cast<const float2*>(
                          P.cnt[lvl] + (size_t)b * hw + p0c));
        const float2* rp2 = reinterpret_cast<const float2*>(
                            P.reg[lvl] + (size_t)b * 4 * hw + p0c);
        float2 L = __ldg(rp2);
        float2 T = __ldg(rp2 + hw2);
        float2 R = __ldg(rp2 + 2 * hw2);
        float2 Bo = __ldg(rp2 + 3 * hw2);
        float4 rt0 = __ldg(reinterpret_cast<const float4*>(reg_t + ti * 4));
        float4 rt1 = __ldg(reinterpret_cast<const float4*>(reg_t + ti * 4 + 4));

        if (m0) {
            float e = exp2f(-fabsf(cv.x) * L2E);
            a_cnt += fmaxf(cv.x, 0.f) - cv.x * ct.x + LN2 * __log2f(1.f + e);
            float wmin = fmaxf(fminf(R.x, rt0.z) + fminf(L.x, rt0.x), 0.f);
            float hmin = fmaxf(fminf(Bo.x, rt0.w) + fminf(T.x, rt0.y), 0.f);
            float ov   = wmin * hmin;
            float uni  = (R.x + L.x) * (Bo.x + T.x) + (rt0.z + rt0.x) * (rt0.w + rt0.y) - ov;
            float wmax = fmaxf(fmaxf(R.x, rt0.z) + fmaxf(L.x, rt0.x), 0.f);
            float hmax = fmaxf(fmaxf(Bo.x, rt0.w) + fmaxf(T.x, rt0.y), 0.f);
            float ga   = wmax * hmax;
            a_reg += 1.f - __fdividef(ov, uni) + __fdividef(ga - uni, fmaxf(ga, 1e-10f));
        }
        if (m1) {
            float e = exp2f(-fabsf(cv.y) * L2E);
            a_cnt += fmaxf(cv.y, 0.f) - cv.y * ct.y + LN2 * __log2f(1.f + e);
            float wmin = fmaxf(fminf(R.y, rt1.z) + fminf(L.y, rt1.x), 0.f);
            float hmin = fmaxf(fminf(Bo.y, rt1.w) + fminf(T.y, rt1.y), 0.f);
            float ov   = wmin * hmin;
            float uni  = (R.y + L.y) * (Bo.y + T.y) + (rt1.z + rt1.x) * (rt1.w + rt1.y) - ov;
            float wmax = fmaxf(fmaxf(R.y, rt1.z) + fmaxf(L.y, rt1.x), 0.f);
            float hmax = fmaxf(fmaxf(Bo.y, rt1.w) + fmaxf(T.y, rt1.y), 0.f);
            float ga   = wmax * hmax;
            a_reg += 1.f - __fdividef(ov, uni) + __fdividef(ga - uni, fmaxf(ga, 1e-10f));
        }

        // focal fixup gathers (matched channel per position, tgt in 1..80)
        const float* cb = P.cls[lvl] + (size_t)b * NCLS * hw;
        if ((unsigned)(tgt0 - 1) < NCLS) {
            float x = __ldg(cb + (size_t)(tgt0 - 1) * hw + p0c);
            a_cls += C_M * focal_one(-x) - C_NM * focal_one(x);
        }
        if ((unsigned)(tgt1 - 1) < NCLS) {
            float x = __ldg(cb + (size_t)(tgt1 - 1) * hw + p0c + 1);
            a_cls += C_M * focal_one(-x) - C_NM * focal_one(x);
        }
    }

    // ---- block reduction into per-block slots (deterministic) ----
    a_cls = wsum(a_cls); a_cnt = wsum(a_cnt); a_reg = wsum(a_reg); a_pos = wsum(a_pos);

    __shared__ float sm[8][4];
    int w = tid >> 5;
    if (lane == 0) { sm[w][0] = a_cls; sm[w][1] = a_cnt; sm[w][2] = a_reg; sm[w][3] = a_pos; }
    __syncthreads();
    if (w == 0 && lane < 8) {
        float x0 = sm[lane][0], x1 = sm[lane][1], x2 = sm[lane][2], x3 = sm[lane][3];
        #pragma unroll
        for (int o = 4; o; o >>= 1) {
            x0 += __shfl_down_sync(0xffu, x0, o);
            x1 += __shfl_down_sync(0xffu, x1, o);
            x2 += __shfl_down_sync(0xffu, x2, o);
            x3 += __shfl_down_sync(0xffu, x3, o);
        }
        if (lane == 0) {
            g_cls[bid] = x0; g_cnt[bid] = x1; g_reg[bid] = x2; g_pos[bid] = x3;
        }
    }

    // ---- last block finishes: parallel final combine ----
    __shared__ bool is_last;
    __threadfence();
    if (tid == 0) is_last = (atomicAdd(&g_sem, 1) == NBLK - 1);
    __syncthreads();
    if (!is_last) return;

    int bt = tid >> 4;       // batch 0..15
    int j  = tid & 15;
    float cls = 0.f, cnt = 0.f, reg = 0.f, pos = 0.f;
    for (int c = j; c < NCHUNK; c += 16) {
        int i = bt * NCHUNK + c;
        cls += g_cls[i]; cnt += g_cnt[i]; reg += g_reg[i]; pos += g_pos[i];
    }
    #pragma unroll
    for (int o = 8; o; o >>= 1) {
        cls += __shfl_down_sync(0xffffffffu, cls, o, 16);
        cnt += __shfl_down_sync(0xffffffffu, cnt, o, 16);
        reg += __shfl_down_sync(0xffffffffu, reg, o, 16);
        pos += __shfl_down_sync(0xffffffffu, pos, o, 16);
    }
    __shared__ float s3[16][3];
    if (j == 0) {
        float np = fmaxf(pos, 1.f);
        s3[bt][0] = cls / np; s3[bt][1] = cnt / np; s3[bt][2] = reg / np;
    }
    __syncthreads();
    if (tid < 16) {
        float c0 = s3[tid][0], c1 = s3[tid][1], c2 = s3[tid][2];
        #pragma unroll
        for (int o = 8; o; o >>= 1) {
            c0 += __shfl_down_sync(0xffffu, c0, o, 16);
            c1 += __shfl_down_sync(0xffffu, c1, o, 16);
            c2 += __shfl_down_sync(0xffffu, c2, o, 16);
        }
        if (tid == 0) {
            c0 *= (1.f / BATCH); c1 *= (1.f / BATCH); c2 *= (1.f / BATCH);
            out[0] = c0; out[1] = c1; out[2] = c2; out[3] = c0 + c1 + c2;
            g_sem = 0;   // reset for next graph replay
        }
    }
}

extern "C" void kernel_launch(void* const* d_in, const int* in_sizes, int n_in,
                              void* d_out, int out_size)
{
    // Three candidate input orderings, disambiguated by element counts:
    //  interleaved (dict):    in_sizes[1] = cnt_p0 = 204800
    //  alphabetical (names):  in_sizes[5] = cls_targets = 273024
    //  grouped (signature):   otherwise
    Ptrs P;
    const float* cnt_t;
    const float* reg_t;
    const int*   cls_t;

    if (in_sizes[1] == 204800) {                    // interleaved
        for (int i = 0; i < 5; i++) {
            P.cls[i] = (const float*)d_in[3 * i + 0];
            P.cnt[i] = (const float*)d_in[3 * i + 1];
            P.reg[i] = (const float*)d_in[3 * i + 2];
        }
        cnt_t = (const float*)d_in[15];
        reg_t = (const float*)d_in[16];
        cls_t = (const int*)d_in[17];
    } else if (in_sizes[5] == 273024) {             // alphabetical
        for (int i = 0; i < 5; i++) {
            P.cls[i] = (const float*)d_in[i];
            P.cnt[i] = (const float*)d_in[6 + i];
            P.reg[i] = (const float*)d_in[12 + i];
        }
        cls_t = (const int*)d_in[5];
        cnt_t = (const float*)d_in[11];
        reg_t = (const float*)d_in[17];
    } else {                                        // grouped (signature order)
        for (int i = 0; i < 5; i++) {
            P.cls[i] = (const float*)d_in[i];
            P.cnt[i] = (const float*)d_in[5 + i];
            P.reg[i] = (const float*)d_in[10 + i];
        }
        cnt_t = (const float*)d_in[15];
        reg_t = (const float*)d_in[16];
        cls_t = (const int*)d_in[17];
    }

    k_main<<<NBLK, 256>>>(P, cnt_t, reg_t, cls_t, (float*)d_out);
}